// round 12
// baseline (speedup 1.0000x reference)
#include <cuda_runtime.h>
#include <cuda_fp16.h>
#include <cstdint>

// ---------------------------------------------------------------------------
// DisenGCN on GB300: fused GEMM(+bias+relu+capsule-normalize) + capsule routing
// N=20000, M=16 neighbors, FEAT=500, d=16, CAPS={8,7,6,5,4,3}, 5 routing iters
// GEMM mainloop + routing phase-A use packed fma.rn.f32x2 (FFMA2).
// Routing: z direct-LDG fp16 mirror; u fp32 smem (LDS.128 = 2 f32x2 operands).
// ---------------------------------------------------------------------------

#define NNODES 20000
#define MNBR   16
#define FEAT   500
#define OUTW   656

// scratch (device globals; no allocation allowed)
__device__ float  g_xnorm [NNODES * 128];  // fp32 normalized x
__device__ __half g_xnormh[NNODES * 128];  // fp16 mirror (neighbor gather)

// ---- packed f32x2 helpers (sm_103a FFMA2 via explicit PTX) ----------------
__device__ __forceinline__ unsigned long long f32x2_pack(float x, float y)
{
    unsigned long long r;
    asm("mov.b64 %0, {%1, %2};" : "=l"(r) : "f"(x), "f"(y));
    return r;
}
__device__ __forceinline__ void f32x2_unpack(unsigned long long v, float& x, float& y)
{
    asm("mov.b64 {%0, %1}, %2;" : "=f"(x), "=f"(y) : "l"(v));
}
__device__ __forceinline__ unsigned long long f32x2_fma(
    unsigned long long a, unsigned long long b, unsigned long long c)
{
    unsigned long long d;
    asm("fma.rn.f32x2 %0, %1, %2, %3;" : "=l"(d) : "l"(a), "l"(b), "l"(c));
    return d;
}
__device__ __forceinline__ unsigned long long h2_to_f32x2(uint32_t h)
{
    __half2 hh = *reinterpret_cast<__half2*>(&h);
    float2 f = __half22float2(hh);
    return f32x2_pack(f.x, f.y);
}

// ---------------------------------------------------------------------------
// GEMM: val[M,N] = (relu?)(A[M,K] @ W[N,K]^T + bias[N])  (R11 winner)
// ---------------------------------------------------------------------------
#define BM 128
#define BN 64
#define BKK 16

__device__ __forceinline__ float4 ldg4_guard(
    const float* __restrict__ P, int gr, int Rdim, int gc, int Kdim, int ld)
{
    float4 v = make_float4(0.f, 0.f, 0.f, 0.f);
    if (gr < Rdim) {
        if (gc + 3 < Kdim) {
            v = *reinterpret_cast<const float4*>(P + (size_t)gr * ld + gc);
        } else {
            const float* row = P + (size_t)gr * ld;
            if (gc + 0 < Kdim) v.x = row[gc + 0];
            if (gc + 1 < Kdim) v.y = row[gc + 1];
            if (gc + 2 < Kdim) v.z = row[gc + 2];
            if (gc + 3 < Kdim) v.w = row[gc + 3];
        }
    }
    return v;
}

template <bool WRITE_RAW>
__global__ void __launch_bounds__(256) gemm_norm_kernel(
    const float* __restrict__ A, int lda,
    const float* __restrict__ W, int ldw,
    const float* __restrict__ bias,
    float* __restrict__ rawOut, int ldo,
    float* __restrict__ xnorm,
    __half* __restrict__ xnormh,
    int Mdim, int Ndim, int Kdim)
{
    __shared__ float As[2][BKK][BM + 4];
    __shared__ float Ws[2][BKK][BN + 4];

    const int tid = threadIdx.x;
    const int tx = tid & 15;
    const int ty = tid >> 4;
    const int bm = blockIdx.y * BM;
    const int bn = blockIdx.x * BN;

    const int ar0 = tid >> 2;
    const int ac4 = (tid & 3) * 4;
    const int ar1 = (tid + 256) >> 2;
    const int wr  = tid >> 2;

    unsigned long long accp[8][2];
    const unsigned long long zz = f32x2_pack(0.f, 0.f);
#pragma unroll
    for (int i = 0; i < 8; ++i) { accp[i][0] = zz; accp[i][1] = zz; }

    const int nk = (Kdim + BKK - 1) / BKK;

    float4 av0, av1, wv0;
    av0 = ldg4_guard(A, bm + ar0, Mdim, 0 + ac4, Kdim, lda);
    av1 = ldg4_guard(A, bm + ar1, Mdim, 0 + ac4, Kdim, lda);
    wv0 = ldg4_guard(W, bn + wr,  Ndim, 0 + ac4, Kdim, ldw);
    {
        As[0][ac4 + 0][ar0] = av0.x; As[0][ac4 + 1][ar0] = av0.y;
        As[0][ac4 + 2][ar0] = av0.z; As[0][ac4 + 3][ar0] = av0.w;
        As[0][ac4 + 0][ar1] = av1.x; As[0][ac4 + 1][ar1] = av1.y;
        As[0][ac4 + 2][ar1] = av1.z; As[0][ac4 + 3][ar1] = av1.w;
        Ws[0][ac4 + 0][wr]  = wv0.x; Ws[0][ac4 + 1][wr]  = wv0.y;
        Ws[0][ac4 + 2][wr]  = wv0.z; Ws[0][ac4 + 3][wr]  = wv0.w;
    }
    __syncthreads();

    for (int it = 0; it < nk; ++it) {
        const int buf = it & 1;
        if (it + 1 < nk) {
            int k0 = (it + 1) * BKK;
            av0 = ldg4_guard(A, bm + ar0, Mdim, k0 + ac4, Kdim, lda);
            av1 = ldg4_guard(A, bm + ar1, Mdim, k0 + ac4, Kdim, lda);
            wv0 = ldg4_guard(W, bn + wr,  Ndim, k0 + ac4, Kdim, ldw);
        }

#pragma unroll
        for (int kk = 0; kk < BKK; ++kk) {
            unsigned long long b01 =
                *reinterpret_cast<const unsigned long long*>(&Ws[buf][kk][tx * 4]);
            unsigned long long b23 =
                *reinterpret_cast<const unsigned long long*>(&Ws[buf][kk][tx * 4 + 2]);
            float a_s[8];
#pragma unroll
            for (int i = 0; i < 8; ++i) a_s[i] = As[buf][kk][ty * 8 + i];
#pragma unroll
            for (int i = 0; i < 8; ++i) {
                unsigned long long aa = f32x2_pack(a_s[i], a_s[i]);
                accp[i][0] = f32x2_fma(aa, b01, accp[i][0]);
                accp[i][1] = f32x2_fma(aa, b23, accp[i][1]);
            }
        }

        if (it + 1 < nk) {
            const int nbuf = buf ^ 1;
            As[nbuf][ac4 + 0][ar0] = av0.x; As[nbuf][ac4 + 1][ar0] = av0.y;
            As[nbuf][ac4 + 2][ar0] = av0.z; As[nbuf][ac4 + 3][ar0] = av0.w;
            As[nbuf][ac4 + 0][ar1] = av1.x; As[nbuf][ac4 + 1][ar1] = av1.y;
            As[nbuf][ac4 + 2][ar1] = av1.z; As[nbuf][ac4 + 3][ar1] = av1.w;
            Ws[nbuf][ac4 + 0][wr]  = wv0.x; Ws[nbuf][ac4 + 1][wr]  = wv0.y;
            Ws[nbuf][ac4 + 2][wr]  = wv0.z; Ws[nbuf][ac4 + 3][wr]  = wv0.w;
            __syncthreads();
        }
    }

    const int gc0 = bn + tx * 4;
    float bvals[4];
#pragma unroll
    for (int j = 0; j < 4; ++j) bvals[j] = (gc0 + j < Ndim) ? bias[gc0 + j] : 0.f;

#pragma unroll
    for (int i = 0; i < 8; ++i) {
        int gr = bm + ty * 8 + i;
        float a0, a1, a2, a3;
        f32x2_unpack(accp[i][0], a0, a1);
        f32x2_unpack(accp[i][1], a2, a3);
        float accv[4] = {a0, a1, a2, a3};
        float v[4];
        float ssq = 0.f;
#pragma unroll
        for (int j = 0; j < 4; ++j) {
            float val = (gc0 + j < Ndim) ? accv[j] + bvals[j] : 0.f;
            if (WRITE_RAW) val = fmaxf(val, 0.f);
            v[j] = val;
            ssq += val * val;
        }
        ssq += __shfl_xor_sync(0xffffffffu, ssq, 1);
        ssq += __shfl_xor_sync(0xffffffffu, ssq, 2);
        float inv = 1.f / fmaxf(sqrtf(ssq), 1e-12f);
        if (gr < Mdim && gc0 < Ndim) {
            if (WRITE_RAW) {
                float4 o = make_float4(v[0], v[1], v[2], v[3]);
                *reinterpret_cast<float4*>(rawOut + (size_t)gr * ldo + gc0) = o;
            }
            float4 no = make_float4(v[0] * inv, v[1] * inv, v[2] * inv, v[3] * inv);
            *reinterpret_cast<float4*>(xnorm + (size_t)gr * Ndim + gc0) = no;
            __half2 h0 = __floats2half2_rn(no.x, no.y);
            __half2 h1 = __floats2half2_rn(no.z, no.w);
            uint2 hp;
            hp.x = *reinterpret_cast<uint32_t*>(&h0);
            hp.y = *reinterpret_cast<uint32_t*>(&h1);
            *reinterpret_cast<uint2*>(xnormh + (size_t)gr * Ndim + gc0) = hp;
        }
    }
}

// ---------------------------------------------------------------------------
// Routing: one CTA per node, NT = 16*P threads.
//  Phase A: z slice pre-converted ONCE to 8 packed f32x2 regs; u is fp32 smem
//           so LDS.128 yields ready f32x2 operands -> 8 FFMA2, zero cvt/iter.
//  Phase B: 8 LDG.64 fp16 z slices (cvt per use); ps fp32 k-major; xs4 fp32.
// ---------------------------------------------------------------------------
__device__ __forceinline__ float4 h4_to_f4(uint32_t lo, uint32_t hi)
{
    __half2 a = *reinterpret_cast<__half2*>(&lo);
    __half2 b = *reinterpret_cast<__half2*>(&hi);
    float2 fa = __half22float2(a);
    float2 fb = __half22float2(b);
    return make_float4(fa.x, fa.y, fb.x, fb.y);
}

template <int K>
__global__ void __launch_bounds__((K > 4) ? 128 : 64, (K > 4) ? 8 : 16)
routing_kernel(
    const float*  __restrict__ xnorm,
    const __half* __restrict__ xnormh,
    const int*    __restrict__ nbid,
    float* __restrict__ outp)
{
    constexpr int P  = (K > 4) ? 8 : 4;
    constexpr int KD = K * 16;
    constexpr int Q  = K * 4;
    constexpr int UP = 20;                 // u row stride (floats): 80B, 16B-aligned
    constexpr int PST = 20;                // ps_t row stride (floats)

    const int n = blockIdx.x;
    const int tid = threadIdx.x;

    __shared__ __align__(16) float u[8 * UP];     // fp32 u
    __shared__ __align__(16) float ps[8 * PST];   // k-major: ps[k*PST + m]
    __shared__ int nb[16];

    if (tid < 16) nb[tid] = __ldg(nbid + n * MNBR + tid);

    // init u = normalized self row (fp32, padded layout)
    if (tid < Q) {
        float4 v = reinterpret_cast<const float4*>(xnorm + (size_t)n * KD)[tid];
        *reinterpret_cast<float4*>(u + (tid >> 2) * UP + (tid & 3) * 4) = v;
    }
    __syncthreads();

    // ---- phase-A: z slice via 2 LDG.128, pre-converted to packed f32x2 ----
    const int mA = tid / P;
    const int kA = tid & (P - 1);
    const bool validA = (kA < K);
    const int kAc = validA ? kA : (K - 1);
    unsigned long long zpp[8];
    {
        const uint4* rowA = reinterpret_cast<const uint4*>(
            xnormh + (size_t)nb[mA] * KD + kAc * 16);
        uint4 r0 = __ldg(rowA);
        uint4 r1 = __ldg(rowA + 1);
        zpp[0] = h2_to_f32x2(r0.x); zpp[1] = h2_to_f32x2(r0.y);
        zpp[2] = h2_to_f32x2(r0.z); zpp[3] = h2_to_f32x2(r0.w);
        zpp[4] = h2_to_f32x2(r1.x); zpp[5] = h2_to_f32x2(r1.y);
        zpp[6] = h2_to_f32x2(r1.z); zpp[7] = h2_to_f32x2(r1.w);
    }

    // ---- phase-B mapping + fp16 z slices: tid = qB*2 + gB (8 m's/thread) ----
    const int qB = tid >> 1;
    const int gB = tid & 1;
    const bool validB = (tid < 2 * Q);
    const int qc = validB ? qB : (Q - 1);
    const int kB = qc >> 2;
    uint2 zah[8];
#pragma unroll
    for (int j = 0; j < 8; ++j)
        zah[j] = __ldg(reinterpret_cast<const uint2*>(
            xnormh + (size_t)nb[8 * gB + j] * KD + qc * 4));
    float4 xs4 = __ldg(reinterpret_cast<const float4*>(xnorm + (size_t)n * KD) + qc);

#pragma unroll
    for (int t = 0; t < 5; ++t) {
        // ---- A: agreement p[m][k] = <z[m,k,:], u[k,:]> via FFMA2 ----
        float p;
        {
            const ulonglong2* uptr = reinterpret_cast<const ulonglong2*>(u + kAc * UP);
            ulonglong2 ua = uptr[0];   // LDS.128: 2 packed f32x2
            ulonglong2 ub = uptr[1];
            ulonglong2 ucp = uptr[2];
            ulonglong2 ud = uptr[3];
            unsigned long long acc0 = f32x2_fma(zpp[0], ua.x, f32x2_pack(0.f, 0.f));
            unsigned long long acc1 = f32x2_fma(zpp[1], ua.y, f32x2_pack(0.f, 0.f));
            acc0 = f32x2_fma(zpp[2], ub.x, acc0);
            acc1 = f32x2_fma(zpp[3], ub.y, acc1);
            acc0 = f32x2_fma(zpp[4], ucp.x, acc0);
            acc1 = f32x2_fma(zpp[5], ucp.y, acc1);
            acc0 = f32x2_fma(zpp[6], ud.x, acc0);
            acc1 = f32x2_fma(zpp[7], ud.y, acc1);
            float l0, h0, l1, h1;
            f32x2_unpack(acc0, l0, h0);
            f32x2_unpack(acc1, l1, h1);
            float pv = (l0 + h0) + (l1 + h1);
            p = validA ? pv : -1e30f;
        }
        // softmax over capsules (no max-sub: |p|<=~1, padding exp -> 0)
        float e = __expf(p);
        float s = e;
        s += __shfl_xor_sync(0xffffffffu, s, 1);
        s += __shfl_xor_sync(0xffffffffu, s, 2);
        if (P == 8) s += __shfl_xor_sync(0xffffffffu, s, 4);
        float pr = __fdividef(e, s);
        if (validA) ps[kA * PST + mA] = pr;
        __syncthreads();

        // ---- B: u[k][:] = xself + sum_m z[m][k][:] * p[m][k] ----
        float4 pa = *reinterpret_cast<const float4*>(ps + kB * PST + 8 * gB);
        float4 pb = *reinterpret_cast<const float4*>(ps + kB * PST + 8 * gB + 4);
        float pm[8] = {pa.x, pa.y, pa.z, pa.w, pb.x, pb.y, pb.z, pb.w};
        float4 acc = make_float4(0.f, 0.f, 0.f, 0.f);
#pragma unroll
        for (int j = 0; j < 8; ++j) {
            float4 zm = h4_to_f4(zah[j].x, zah[j].y);
            acc.x += zm.x * pm[j]; acc.y += zm.y * pm[j];
            acc.z += zm.z * pm[j]; acc.w += zm.w * pm[j];
        }
        acc.x += __shfl_xor_sync(0xffffffffu, acc.x, 1);
        acc.y += __shfl_xor_sync(0xffffffffu, acc.y, 1);
        acc.z += __shfl_xor_sync(0xffffffffu, acc.z, 1);
        acc.w += __shfl_xor_sync(0xffffffffu, acc.w, 1);
        acc.x += xs4.x; acc.y += xs4.y; acc.z += xs4.z; acc.w += xs4.w;

        if (t < 4) {
            float sq = acc.x * acc.x + acc.y * acc.y + acc.z * acc.z + acc.w * acc.w;
            sq += __shfl_xor_sync(0xffffffffu, sq, 2);
            sq += __shfl_xor_sync(0xffffffffu, sq, 4);
            float inv = rsqrtf(fmaxf(sq, 1e-24f));
            if (validB && gB == 0) {
                float4 o = make_float4(acc.x * inv, acc.y * inv, acc.z * inv, acc.w * inv);
                *reinterpret_cast<float4*>(u + kB * UP + (qB & 3) * 4) = o;
            }
            __syncthreads();
        } else if (validB && gB == 0) {
            float4 o = make_float4(fmaxf(acc.x, 0.f), fmaxf(acc.y, 0.f),
                                   fmaxf(acc.z, 0.f), fmaxf(acc.w, 0.f));
            *reinterpret_cast<float4*>(outp + (size_t)n * OUTW + qB * 4) = o;
        }
    }
}

// ---------------------------------------------------------------------------
// host orchestration
// ---------------------------------------------------------------------------
extern "C" void kernel_launch(void* const* d_in, const int* in_sizes, int n_in,
                              void* d_out, int out_size)
{
    (void)in_sizes; (void)n_in; (void)out_size;
    const float* feature = (const float*)d_in[0];
    const int*   nbid    = (const int*)d_in[1];
    const float* pca_w   = (const float*)d_in[2];
    const float* pca_b   = (const float*)d_in[3];
    const float* W[6]  = {nullptr, (const float*)d_in[4], (const float*)d_in[6],
                          (const float*)d_in[8], (const float*)d_in[10], (const float*)d_in[12]};
    const float* Bb[6] = {nullptr, (const float*)d_in[5], (const float*)d_in[7],
                          (const float*)d_in[9], (const float*)d_in[11], (const float*)d_in[13]};
    float* out = (float*)d_out;

    static const int caps[6]   = {8, 7, 6, 5, 4, 3};
    static const int coloff[7] = {0, 128, 256, 368, 464, 544, 608};

    float* xnorm;
    __half* xnormh;
    cudaGetSymbolAddress((void**)&xnorm,  g_xnorm);
    cudaGetSymbolAddress((void**)&xnormh, g_xnormh);

    const int mblocks = (NNODES + BM - 1) / BM;   // 157

    // PCA: x0 = relu(feature @ pca_w.T + pca_b) -> out[:,0:128] + xnorm(+h)
    {
        dim3 grid((128 + BN - 1) / BN, mblocks);
        gemm_norm_kernel<true><<<grid, 256>>>(feature, FEAT, pca_w, FEAT, pca_b,
                                              out, OUTW, xnorm, xnormh,
                                              NNODES, 128, FEAT);
    }

    for (int i = 0; i < 6; ++i) {
        int k = caps[i];
        int kd = k * 16;
        if (i > 0) {
            int fin = caps[i - 1] * 16;
            dim3 grid((kd + BN - 1) / BN, mblocks);
            gemm_norm_kernel<false><<<grid, 256>>>(out + coloff[i], OUTW,
                                                   W[i], fin, Bb[i],
                                                   nullptr, 0, xnorm, xnormh,
                                                   NNODES, kd, fin);
        }
        float* dst = out + coloff[i + 1];
        switch (k) {
            case 8: routing_kernel<8><<<NNODES, 128>>>(xnorm, xnormh, nbid, dst); break;
            case 7: routing_kernel<7><<<NNODES, 128>>>(xnorm, xnormh, nbid, dst); break;
            case 6: routing_kernel<6><<<NNODES, 128>>>(xnorm, xnormh, nbid, dst); break;
            case 5: routing_kernel<5><<<NNODES, 128>>>(xnorm, xnormh, nbid, dst); break;
            case 4: routing_kernel<4><<<NNODES, 64>>>(xnorm, xnormh, nbid, dst); break;
            case 3: routing_kernel<3><<<NNODES, 64>>>(xnorm, xnormh, nbid, dst); break;
        }
    }
}

// round 13
// speedup vs baseline: 1.1441x; 1.1441x over previous
#include <cuda_runtime.h>
#include <cuda_fp16.h>
#include <cstdint>

// ---------------------------------------------------------------------------
// DisenGCN on GB300: fused GEMM(+bias+relu+capsule-normalize) + capsule routing
// N=20000, M=16 neighbors, FEAT=500, d=16, CAPS={8,7,6,5,4,3}, 5 routing iters
// GEMM mainloop: packed fma.rn.f32x2 (FFMA2). Routing: z direct-LDG fp16
// mirror, fp16 u smem, phase-A dot in HFMA2 (split accumulators), fp32 agg.
// ---------------------------------------------------------------------------

#define NNODES 20000
#define MNBR   16
#define FEAT   500
#define OUTW   656

// scratch (device globals; no allocation allowed)
__device__ float  g_xnorm [NNODES * 128];  // fp32 normalized x
__device__ __half g_xnormh[NNODES * 128];  // fp16 mirror (neighbor gather)

// ---- packed f32x2 helpers (sm_103a FFMA2 via explicit PTX) ----------------
__device__ __forceinline__ unsigned long long f32x2_pack(float x, float y)
{
    unsigned long long r;
    asm("mov.b64 %0, {%1, %2};" : "=l"(r) : "f"(x), "f"(y));
    return r;
}
__device__ __forceinline__ void f32x2_unpack(unsigned long long v, float& x, float& y)
{
    asm("mov.b64 {%0, %1}, %2;" : "=f"(x), "=f"(y) : "l"(v));
}
__device__ __forceinline__ unsigned long long f32x2_fma(
    unsigned long long a, unsigned long long b, unsigned long long c)
{
    unsigned long long d;
    asm("fma.rn.f32x2 %0, %1, %2, %3;" : "=l"(d) : "l"(a), "l"(b), "l"(c));
    return d;
}
__device__ __forceinline__ __half2 u32_h2(uint32_t v)
{
    return *reinterpret_cast<__half2*>(&v);
}

// ---------------------------------------------------------------------------
// GEMM: val[M,N] = (relu?)(A[M,K] @ W[N,K]^T + bias[N])  (R11 winner)
// ---------------------------------------------------------------------------
#define BM 128
#define BN 64
#define BKK 16

__device__ __forceinline__ float4 ldg4_guard(
    const float* __restrict__ P, int gr, int Rdim, int gc, int Kdim, int ld)
{
    float4 v = make_float4(0.f, 0.f, 0.f, 0.f);
    if (gr < Rdim) {
        if (gc + 3 < Kdim) {
            v = *reinterpret_cast<const float4*>(P + (size_t)gr * ld + gc);
        } else {
            const float* row = P + (size_t)gr * ld;
            if (gc + 0 < Kdim) v.x = row[gc + 0];
            if (gc + 1 < Kdim) v.y = row[gc + 1];
            if (gc + 2 < Kdim) v.z = row[gc + 2];
            if (gc + 3 < Kdim) v.w = row[gc + 3];
        }
    }
    return v;
}

template <bool WRITE_RAW>
__global__ void __launch_bounds__(256) gemm_norm_kernel(
    const float* __restrict__ A, int lda,
    const float* __restrict__ W, int ldw,
    const float* __restrict__ bias,
    float* __restrict__ rawOut, int ldo,
    float* __restrict__ xnorm,
    __half* __restrict__ xnormh,
    int Mdim, int Ndim, int Kdim)
{
    __shared__ float As[2][BKK][BM + 4];
    __shared__ float Ws[2][BKK][BN + 4];

    const int tid = threadIdx.x;
    const int tx = tid & 15;
    const int ty = tid >> 4;
    const int bm = blockIdx.y * BM;
    const int bn = blockIdx.x * BN;

    const int ar0 = tid >> 2;
    const int ac4 = (tid & 3) * 4;
    const int ar1 = (tid + 256) >> 2;
    const int wr  = tid >> 2;

    unsigned long long accp[8][2];
    const unsigned long long zz = f32x2_pack(0.f, 0.f);
#pragma unroll
    for (int i = 0; i < 8; ++i) { accp[i][0] = zz; accp[i][1] = zz; }

    const int nk = (Kdim + BKK - 1) / BKK;

    float4 av0, av1, wv0;
    av0 = ldg4_guard(A, bm + ar0, Mdim, 0 + ac4, Kdim, lda);
    av1 = ldg4_guard(A, bm + ar1, Mdim, 0 + ac4, Kdim, lda);
    wv0 = ldg4_guard(W, bn + wr,  Ndim, 0 + ac4, Kdim, ldw);
    {
        As[0][ac4 + 0][ar0] = av0.x; As[0][ac4 + 1][ar0] = av0.y;
        As[0][ac4 + 2][ar0] = av0.z; As[0][ac4 + 3][ar0] = av0.w;
        As[0][ac4 + 0][ar1] = av1.x; As[0][ac4 + 1][ar1] = av1.y;
        As[0][ac4 + 2][ar1] = av1.z; As[0][ac4 + 3][ar1] = av1.w;
        Ws[0][ac4 + 0][wr]  = wv0.x; Ws[0][ac4 + 1][wr]  = wv0.y;
        Ws[0][ac4 + 2][wr]  = wv0.z; Ws[0][ac4 + 3][wr]  = wv0.w;
    }
    __syncthreads();

    for (int it = 0; it < nk; ++it) {
        const int buf = it & 1;
        if (it + 1 < nk) {
            int k0 = (it + 1) * BKK;
            av0 = ldg4_guard(A, bm + ar0, Mdim, k0 + ac4, Kdim, lda);
            av1 = ldg4_guard(A, bm + ar1, Mdim, k0 + ac4, Kdim, lda);
            wv0 = ldg4_guard(W, bn + wr,  Ndim, k0 + ac4, Kdim, ldw);
        }

#pragma unroll
        for (int kk = 0; kk < BKK; ++kk) {
            unsigned long long b01 =
                *reinterpret_cast<const unsigned long long*>(&Ws[buf][kk][tx * 4]);
            unsigned long long b23 =
                *reinterpret_cast<const unsigned long long*>(&Ws[buf][kk][tx * 4 + 2]);
            float a_s[8];
#pragma unroll
            for (int i = 0; i < 8; ++i) a_s[i] = As[buf][kk][ty * 8 + i];
#pragma unroll
            for (int i = 0; i < 8; ++i) {
                unsigned long long aa = f32x2_pack(a_s[i], a_s[i]);
                accp[i][0] = f32x2_fma(aa, b01, accp[i][0]);
                accp[i][1] = f32x2_fma(aa, b23, accp[i][1]);
            }
        }

        if (it + 1 < nk) {
            const int nbuf = buf ^ 1;
            As[nbuf][ac4 + 0][ar0] = av0.x; As[nbuf][ac4 + 1][ar0] = av0.y;
            As[nbuf][ac4 + 2][ar0] = av0.z; As[nbuf][ac4 + 3][ar0] = av0.w;
            As[nbuf][ac4 + 0][ar1] = av1.x; As[nbuf][ac4 + 1][ar1] = av1.y;
            As[nbuf][ac4 + 2][ar1] = av1.z; As[nbuf][ac4 + 3][ar1] = av1.w;
            Ws[nbuf][ac4 + 0][wr]  = wv0.x; Ws[nbuf][ac4 + 1][wr]  = wv0.y;
            Ws[nbuf][ac4 + 2][wr]  = wv0.z; Ws[nbuf][ac4 + 3][wr]  = wv0.w;
            __syncthreads();
        }
    }

    const int gc0 = bn + tx * 4;
    float bvals[4];
#pragma unroll
    for (int j = 0; j < 4; ++j) bvals[j] = (gc0 + j < Ndim) ? bias[gc0 + j] : 0.f;

#pragma unroll
    for (int i = 0; i < 8; ++i) {
        int gr = bm + ty * 8 + i;
        float a0, a1, a2, a3;
        f32x2_unpack(accp[i][0], a0, a1);
        f32x2_unpack(accp[i][1], a2, a3);
        float accv[4] = {a0, a1, a2, a3};
        float v[4];
        float ssq = 0.f;
#pragma unroll
        for (int j = 0; j < 4; ++j) {
            float val = (gc0 + j < Ndim) ? accv[j] + bvals[j] : 0.f;
            if (WRITE_RAW) val = fmaxf(val, 0.f);
            v[j] = val;
            ssq += val * val;
        }
        ssq += __shfl_xor_sync(0xffffffffu, ssq, 1);
        ssq += __shfl_xor_sync(0xffffffffu, ssq, 2);
        float inv = 1.f / fmaxf(sqrtf(ssq), 1e-12f);
        if (gr < Mdim && gc0 < Ndim) {
            if (WRITE_RAW) {
                float4 o = make_float4(v[0], v[1], v[2], v[3]);
                *reinterpret_cast<float4*>(rawOut + (size_t)gr * ldo + gc0) = o;
            }
            float4 no = make_float4(v[0] * inv, v[1] * inv, v[2] * inv, v[3] * inv);
            *reinterpret_cast<float4*>(xnorm + (size_t)gr * Ndim + gc0) = no;
            __half2 h0 = __floats2half2_rn(no.x, no.y);
            __half2 h1 = __floats2half2_rn(no.z, no.w);
            uint2 hp;
            hp.x = *reinterpret_cast<uint32_t*>(&h0);
            hp.y = *reinterpret_cast<uint32_t*>(&h1);
            *reinterpret_cast<uint2*>(xnormh + (size_t)gr * Ndim + gc0) = hp;
        }
    }
}

// ---------------------------------------------------------------------------
// Routing (R11 base + HFMA2 phase-A): one CTA per node, NT = 16*P threads.
//  Phase A: z slice packed fp16 regs; u row = 2 LDS.128 fp16; dot via 8 HFMA2
//           with two split half2 accumulators -> fp32 at the end.
//  Phase B: 8 LDG.64 fp16 z slices; ps fp32 k-major; xs4 exact fp32; fp32 agg.
// ---------------------------------------------------------------------------
__device__ __forceinline__ float4 h4_to_f4(uint32_t lo, uint32_t hi)
{
    __half2 a = *reinterpret_cast<__half2*>(&lo);
    __half2 b = *reinterpret_cast<__half2*>(&hi);
    float2 fa = __half22float2(a);
    float2 fb = __half22float2(b);
    return make_float4(fa.x, fa.y, fb.x, fb.y);
}

template <int K>
__global__ void __launch_bounds__((K > 4) ? 128 : 64, (K > 4) ? 8 : 16)
routing_kernel(
    const float*  __restrict__ xnorm,
    const __half* __restrict__ xnormh,
    const int*    __restrict__ nbid,
    float* __restrict__ outp)
{
    constexpr int P  = (K > 4) ? 8 : 4;
    constexpr int KD = K * 16;
    constexpr int Q  = K * 4;
    constexpr int UPH = 24;                // u row stride (halves): 48B rows
    constexpr int PST = 20;                // ps_t row stride (floats)

    const int n = blockIdx.x;
    const int tid = threadIdx.x;

    __shared__ __align__(16) __half uh[8 * UPH];
    __shared__ __align__(16) float ps[8 * PST];
    __shared__ int nb[16];

    if (tid < 16) nb[tid] = __ldg(nbid + n * MNBR + tid);

    if (tid < Q) {
        float4 v = reinterpret_cast<const float4*>(xnorm + (size_t)n * KD)[tid];
        __half2 h0 = __floats2half2_rn(v.x, v.y);
        __half2 h1 = __floats2half2_rn(v.z, v.w);
        uint2 hp;
        hp.x = *reinterpret_cast<uint32_t*>(&h0);
        hp.y = *reinterpret_cast<uint32_t*>(&h1);
        *reinterpret_cast<uint2*>(uh + (tid >> 2) * UPH + (tid & 3) * 4) = hp;
    }
    __syncthreads();

    const int mA = tid / P;
    const int kA = tid & (P - 1);
    const bool validA = (kA < K);
    const int kAc = validA ? kA : (K - 1);
    uint4 zr0, zr1;
    {
        const uint4* rowA = reinterpret_cast<const uint4*>(
            xnormh + (size_t)nb[mA] * KD + kAc * 16);
        zr0 = __ldg(rowA);
        zr1 = __ldg(rowA + 1);
    }

    const int qB = tid >> 1;
    const int gB = tid & 1;
    const bool validB = (tid < 2 * Q);
    const int qc = validB ? qB : (Q - 1);
    const int kB = qc >> 2;
    uint2 zah[8];
#pragma unroll
    for (int j = 0; j < 8; ++j)
        zah[j] = __ldg(reinterpret_cast<const uint2*>(
            xnormh + (size_t)nb[8 * gB + j] * KD + qc * 4));
    float4 xs4 = __ldg(reinterpret_cast<const float4*>(xnorm + (size_t)n * KD) + qc);

#pragma unroll
    for (int t = 0; t < 5; ++t) {
        // ---- A: agreement p[m][k] = <z[m,k,:], u[k,:]> via HFMA2 ----
        float p;
        {
            const uint4* uptr = reinterpret_cast<const uint4*>(uh + kAc * UPH);
            uint4 u0 = uptr[0];
            uint4 u1 = uptr[1];
            __half2 za0 = __float2half2_rn(0.f);
            __half2 za1 = __float2half2_rn(0.f);
            za0 = __hfma2(u32_h2(zr0.x), u32_h2(u0.x), za0);
            za1 = __hfma2(u32_h2(zr0.y), u32_h2(u0.y), za1);
            za0 = __hfma2(u32_h2(zr0.z), u32_h2(u0.z), za0);
            za1 = __hfma2(u32_h2(zr0.w), u32_h2(u0.w), za1);
            za0 = __hfma2(u32_h2(zr1.x), u32_h2(u1.x), za0);
            za1 = __hfma2(u32_h2(zr1.y), u32_h2(u1.y), za1);
            za0 = __hfma2(u32_h2(zr1.z), u32_h2(u1.z), za0);
            za1 = __hfma2(u32_h2(zr1.w), u32_h2(u1.w), za1);
            float2 f0 = __half22float2(za0);
            float2 f1 = __half22float2(za1);
            float pv = (f0.x + f0.y) + (f1.x + f1.y);
            p = validA ? pv : -1e30f;
        }
        // softmax over capsules (no max-sub: |p|<=~1, padding exp -> 0)
        float e = __expf(p);
        float s = e;
        s += __shfl_xor_sync(0xffffffffu, s, 1);
        s += __shfl_xor_sync(0xffffffffu, s, 2);
        if (P == 8) s += __shfl_xor_sync(0xffffffffu, s, 4);
        float pr = __fdividef(e, s);
        if (validA) ps[kA * PST + mA] = pr;
        __syncthreads();

        // ---- B: u[k][:] = xself + sum_m z[m][k][:] * p[m][k] (fp32) ----
        float4 pa = *reinterpret_cast<const float4*>(ps + kB * PST + 8 * gB);
        float4 pb = *reinterpret_cast<const float4*>(ps + kB * PST + 8 * gB + 4);
        float pm[8] = {pa.x, pa.y, pa.z, pa.w, pb.x, pb.y, pb.z, pb.w};
        float4 acc = make_float4(0.f, 0.f, 0.f, 0.f);
#pragma unroll
        for (int j = 0; j < 8; ++j) {
            float4 zm = h4_to_f4(zah[j].x, zah[j].y);
            acc.x += zm.x * pm[j]; acc.y += zm.y * pm[j];
            acc.z += zm.z * pm[j]; acc.w += zm.w * pm[j];
        }
        acc.x += __shfl_xor_sync(0xffffffffu, acc.x, 1);
        acc.y += __shfl_xor_sync(0xffffffffu, acc.y, 1);
        acc.z += __shfl_xor_sync(0xffffffffu, acc.z, 1);
        acc.w += __shfl_xor_sync(0xffffffffu, acc.w, 1);
        acc.x += xs4.x; acc.y += xs4.y; acc.z += xs4.z; acc.w += xs4.w;

        if (t < 4) {
            float sq = acc.x * acc.x + acc.y * acc.y + acc.z * acc.z + acc.w * acc.w;
            sq += __shfl_xor_sync(0xffffffffu, sq, 2);
            sq += __shfl_xor_sync(0xffffffffu, sq, 4);
            float inv = rsqrtf(fmaxf(sq, 1e-24f));
            if (validB && gB == 0) {
                __half2 h0 = __floats2half2_rn(acc.x * inv, acc.y * inv);
                __half2 h1 = __floats2half2_rn(acc.z * inv, acc.w * inv);
                uint2 hp;
                hp.x = *reinterpret_cast<uint32_t*>(&h0);
                hp.y = *reinterpret_cast<uint32_t*>(&h1);
                *reinterpret_cast<uint2*>(uh + kB * UPH + (qB & 3) * 4) = hp;
            }
            __syncthreads();
        } else if (validB && gB == 0) {
            float4 o = make_float4(fmaxf(acc.x, 0.f), fmaxf(acc.y, 0.f),
                                   fmaxf(acc.z, 0.f), fmaxf(acc.w, 0.f));
            *reinterpret_cast<float4*>(outp + (size_t)n * OUTW + qB * 4) = o;
        }
    }
}

// ---------------------------------------------------------------------------
// host orchestration
// ---------------------------------------------------------------------------
extern "C" void kernel_launch(void* const* d_in, const int* in_sizes, int n_in,
                              void* d_out, int out_size)
{
    (void)in_sizes; (void)n_in; (void)out_size;
    const float* feature = (const float*)d_in[0];
    const int*   nbid    = (const int*)d_in[1];
    const float* pca_w   = (const float*)d_in[2];
    const float* pca_b   = (const float*)d_in[3];
    const float* W[6]  = {nullptr, (const float*)d_in[4], (const float*)d_in[6],
                          (const float*)d_in[8], (const float*)d_in[10], (const float*)d_in[12]};
    const float* Bb[6] = {nullptr, (const float*)d_in[5], (const float*)d_in[7],
                          (const float*)d_in[9], (const float*)d_in[11], (const float*)d_in[13]};
    float* out = (float*)d_out;

    static const int caps[6]   = {8, 7, 6, 5, 4, 3};
    static const int coloff[7] = {0, 128, 256, 368, 464, 544, 608};

    float* xnorm;
    __half* xnormh;
    cudaGetSymbolAddress((void**)&xnorm,  g_xnorm);
    cudaGetSymbolAddress((void**)&xnormh, g_xnormh);

    const int mblocks = (NNODES + BM - 1) / BM;   // 157

    // PCA: x0 = relu(feature @ pca_w.T + pca_b) -> out[:,0:128] + xnorm(+h)
    {
        dim3 grid((128 + BN - 1) / BN, mblocks);
        gemm_norm_kernel<true><<<grid, 256>>>(feature, FEAT, pca_w, FEAT, pca_b,
                                              out, OUTW, xnorm, xnormh,
                                              NNODES, 128, FEAT);
    }

    for (int i = 0; i < 6; ++i) {
        int k = caps[i];
        int kd = k * 16;
        if (i > 0) {
            int fin = caps[i - 1] * 16;
            dim3 grid((kd + BN - 1) / BN, mblocks);
            gemm_norm_kernel<false><<<grid, 256>>>(out + coloff[i], OUTW,
                                                   W[i], fin, Bb[i],
                                                   nullptr, 0, xnorm, xnormh,
                                                   NNODES, kd, fin);
        }
        float* dst = out + coloff[i + 1];
        switch (k) {
            case 8: routing_kernel<8><<<NNODES, 128>>>(xnorm, xnormh, nbid, dst); break;
            case 7: routing_kernel<7><<<NNODES, 128>>>(xnorm, xnormh, nbid, dst); break;
            case 6: routing_kernel<6><<<NNODES, 128>>>(xnorm, xnormh, nbid, dst); break;
            case 5: routing_kernel<5><<<NNODES, 128>>>(xnorm, xnormh, nbid, dst); break;
            case 4: routing_kernel<4><<<NNODES, 64>>>(xnorm, xnormh, nbid, dst); break;
            case 3: routing_kernel<3><<<NNODES, 64>>>(xnorm, xnormh, nbid, dst); break;
        }
    }
}

// round 14
// speedup vs baseline: 1.2124x; 1.0597x over previous
#include <cuda_runtime.h>
#include <cuda_fp16.h>
#include <cstdint>

// ---------------------------------------------------------------------------
// DisenGCN on GB300: fused GEMM(+bias+relu+capsule-normalize) + capsule routing
// N=20000, M=16 neighbors, FEAT=500, d=16, CAPS={8,7,6,5,4,3}, 5 routing iters
// GEMM mainloop: packed fma.rn.f32x2 (FFMA2). Routing: fully fp16-operand
// datapath (z, u, ps) with split half2 accumulators; reductions/output fp32.
// ---------------------------------------------------------------------------

#define NNODES 20000
#define MNBR   16
#define FEAT   500
#define OUTW   656

// scratch (device globals; no allocation allowed)
__device__ float  g_xnorm [NNODES * 128];  // fp32 normalized x
__device__ __half g_xnormh[NNODES * 128];  // fp16 mirror (neighbor gather)

// ---- packed f32x2 helpers (sm_103a FFMA2 via explicit PTX) ----------------
__device__ __forceinline__ unsigned long long f32x2_pack(float x, float y)
{
    unsigned long long r;
    asm("mov.b64 %0, {%1, %2};" : "=l"(r) : "f"(x), "f"(y));
    return r;
}
__device__ __forceinline__ void f32x2_unpack(unsigned long long v, float& x, float& y)
{
    asm("mov.b64 {%0, %1}, %2;" : "=f"(x), "=f"(y) : "l"(v));
}
__device__ __forceinline__ unsigned long long f32x2_fma(
    unsigned long long a, unsigned long long b, unsigned long long c)
{
    unsigned long long d;
    asm("fma.rn.f32x2 %0, %1, %2, %3;" : "=l"(d) : "l"(a), "l"(b), "l"(c));
    return d;
}
__device__ __forceinline__ __half2 u32_h2(uint32_t v)
{
    return *reinterpret_cast<__half2*>(&v);
}

// ---------------------------------------------------------------------------
// GEMM: val[M,N] = (relu?)(A[M,K] @ W[N,K]^T + bias[N])  (R11 winner)
// ---------------------------------------------------------------------------
#define BM 128
#define BN 64
#define BKK 16

__device__ __forceinline__ float4 ldg4_guard(
    const float* __restrict__ P, int gr, int Rdim, int gc, int Kdim, int ld)
{
    float4 v = make_float4(0.f, 0.f, 0.f, 0.f);
    if (gr < Rdim) {
        if (gc + 3 < Kdim) {
            v = *reinterpret_cast<const float4*>(P + (size_t)gr * ld + gc);
        } else {
            const float* row = P + (size_t)gr * ld;
            if (gc + 0 < Kdim) v.x = row[gc + 0];
            if (gc + 1 < Kdim) v.y = row[gc + 1];
            if (gc + 2 < Kdim) v.z = row[gc + 2];
            if (gc + 3 < Kdim) v.w = row[gc + 3];
        }
    }
    return v;
}

template <bool WRITE_RAW>
__global__ void __launch_bounds__(256) gemm_norm_kernel(
    const float* __restrict__ A, int lda,
    const float* __restrict__ W, int ldw,
    const float* __restrict__ bias,
    float* __restrict__ rawOut, int ldo,
    float* __restrict__ xnorm,
    __half* __restrict__ xnormh,
    int Mdim, int Ndim, int Kdim)
{
    __shared__ float As[2][BKK][BM + 4];
    __shared__ float Ws[2][BKK][BN + 4];

    const int tid = threadIdx.x;
    const int tx = tid & 15;
    const int ty = tid >> 4;
    const int bm = blockIdx.y * BM;
    const int bn = blockIdx.x * BN;

    const int ar0 = tid >> 2;
    const int ac4 = (tid & 3) * 4;
    const int ar1 = (tid + 256) >> 2;
    const int wr  = tid >> 2;

    unsigned long long accp[8][2];
    const unsigned long long zz = f32x2_pack(0.f, 0.f);
#pragma unroll
    for (int i = 0; i < 8; ++i) { accp[i][0] = zz; accp[i][1] = zz; }

    const int nk = (Kdim + BKK - 1) / BKK;

    float4 av0, av1, wv0;
    av0 = ldg4_guard(A, bm + ar0, Mdim, 0 + ac4, Kdim, lda);
    av1 = ldg4_guard(A, bm + ar1, Mdim, 0 + ac4, Kdim, lda);
    wv0 = ldg4_guard(W, bn + wr,  Ndim, 0 + ac4, Kdim, ldw);
    {
        As[0][ac4 + 0][ar0] = av0.x; As[0][ac4 + 1][ar0] = av0.y;
        As[0][ac4 + 2][ar0] = av0.z; As[0][ac4 + 3][ar0] = av0.w;
        As[0][ac4 + 0][ar1] = av1.x; As[0][ac4 + 1][ar1] = av1.y;
        As[0][ac4 + 2][ar1] = av1.z; As[0][ac4 + 3][ar1] = av1.w;
        Ws[0][ac4 + 0][wr]  = wv0.x; Ws[0][ac4 + 1][wr]  = wv0.y;
        Ws[0][ac4 + 2][wr]  = wv0.z; Ws[0][ac4 + 3][wr]  = wv0.w;
    }
    __syncthreads();

    for (int it = 0; it < nk; ++it) {
        const int buf = it & 1;
        if (it + 1 < nk) {
            int k0 = (it + 1) * BKK;
            av0 = ldg4_guard(A, bm + ar0, Mdim, k0 + ac4, Kdim, lda);
            av1 = ldg4_guard(A, bm + ar1, Mdim, k0 + ac4, Kdim, lda);
            wv0 = ldg4_guard(W, bn + wr,  Ndim, k0 + ac4, Kdim, ldw);
        }

#pragma unroll
        for (int kk = 0; kk < BKK; ++kk) {
            unsigned long long b01 =
                *reinterpret_cast<const unsigned long long*>(&Ws[buf][kk][tx * 4]);
            unsigned long long b23 =
                *reinterpret_cast<const unsigned long long*>(&Ws[buf][kk][tx * 4 + 2]);
            float a_s[8];
#pragma unroll
            for (int i = 0; i < 8; ++i) a_s[i] = As[buf][kk][ty * 8 + i];
#pragma unroll
            for (int i = 0; i < 8; ++i) {
                unsigned long long aa = f32x2_pack(a_s[i], a_s[i]);
                accp[i][0] = f32x2_fma(aa, b01, accp[i][0]);
                accp[i][1] = f32x2_fma(aa, b23, accp[i][1]);
            }
        }

        if (it + 1 < nk) {
            const int nbuf = buf ^ 1;
            As[nbuf][ac4 + 0][ar0] = av0.x; As[nbuf][ac4 + 1][ar0] = av0.y;
            As[nbuf][ac4 + 2][ar0] = av0.z; As[nbuf][ac4 + 3][ar0] = av0.w;
            As[nbuf][ac4 + 0][ar1] = av1.x; As[nbuf][ac4 + 1][ar1] = av1.y;
            As[nbuf][ac4 + 2][ar1] = av1.z; As[nbuf][ac4 + 3][ar1] = av1.w;
            Ws[nbuf][ac4 + 0][wr]  = wv0.x; Ws[nbuf][ac4 + 1][wr]  = wv0.y;
            Ws[nbuf][ac4 + 2][wr]  = wv0.z; Ws[nbuf][ac4 + 3][wr]  = wv0.w;
            __syncthreads();
        }
    }

    const int gc0 = bn + tx * 4;
    float bvals[4];
#pragma unroll
    for (int j = 0; j < 4; ++j) bvals[j] = (gc0 + j < Ndim) ? bias[gc0 + j] : 0.f;

#pragma unroll
    for (int i = 0; i < 8; ++i) {
        int gr = bm + ty * 8 + i;
        float a0, a1, a2, a3;
        f32x2_unpack(accp[i][0], a0, a1);
        f32x2_unpack(accp[i][1], a2, a3);
        float accv[4] = {a0, a1, a2, a3};
        float v[4];
        float ssq = 0.f;
#pragma unroll
        for (int j = 0; j < 4; ++j) {
            float val = (gc0 + j < Ndim) ? accv[j] + bvals[j] : 0.f;
            if (WRITE_RAW) val = fmaxf(val, 0.f);
            v[j] = val;
            ssq += val * val;
        }
        ssq += __shfl_xor_sync(0xffffffffu, ssq, 1);
        ssq += __shfl_xor_sync(0xffffffffu, ssq, 2);
        float inv = 1.f / fmaxf(sqrtf(ssq), 1e-12f);
        if (gr < Mdim && gc0 < Ndim) {
            if (WRITE_RAW) {
                float4 o = make_float4(v[0], v[1], v[2], v[3]);
                *reinterpret_cast<float4*>(rawOut + (size_t)gr * ldo + gc0) = o;
            }
            float4 no = make_float4(v[0] * inv, v[1] * inv, v[2] * inv, v[3] * inv);
            *reinterpret_cast<float4*>(xnorm + (size_t)gr * Ndim + gc0) = no;
            __half2 h0 = __floats2half2_rn(no.x, no.y);
            __half2 h1 = __floats2half2_rn(no.z, no.w);
            uint2 hp;
            hp.x = *reinterpret_cast<uint32_t*>(&h0);
            hp.y = *reinterpret_cast<uint32_t*>(&h1);
            *reinterpret_cast<uint2*>(xnormh + (size_t)gr * Ndim + gc0) = hp;
        }
    }
}

// ---------------------------------------------------------------------------
// Routing: one CTA per node, NT = 16*P threads. Full fp16-operand datapath.
//  Phase A: z packed fp16 regs; u = 2 LDS.128 fp16; 8 HFMA2 split-acc dot.
//  Phase B: ps stored fp16 (k-major, stride 24 halves) -> 1 LDS.128 per
//           thread; pm broadcast pairs via byte_perm; 16 HFMA2 with four
//           depth-4 half2 accumulators; g-reduce/ssq/output fp32.
// ---------------------------------------------------------------------------
template <int K>
__global__ void __launch_bounds__((K > 4) ? 128 : 64, (K > 4) ? 8 : 16)
routing_kernel(
    const float*  __restrict__ xnorm,
    const __half* __restrict__ xnormh,
    const int*    __restrict__ nbid,
    float* __restrict__ outp)
{
    constexpr int P  = (K > 4) ? 8 : 4;
    constexpr int KD = K * 16;
    constexpr int Q  = K * 4;
    constexpr int UPH = 24;                // u row stride (halves): 48B rows
    constexpr int PSH = 24;                // ps row stride (halves): 48B rows

    const int n = blockIdx.x;
    const int tid = threadIdx.x;

    __shared__ __align__(16) __half uh[8 * UPH];
    __shared__ __align__(16) __half psh[8 * PSH];  // k-major: psh[k*PSH + m]
    __shared__ int nb[16];

    if (tid < 16) nb[tid] = __ldg(nbid + n * MNBR + tid);

    if (tid < Q) {
        float4 v = reinterpret_cast<const float4*>(xnorm + (size_t)n * KD)[tid];
        __half2 h0 = __floats2half2_rn(v.x, v.y);
        __half2 h1 = __floats2half2_rn(v.z, v.w);
        uint2 hp;
        hp.x = *reinterpret_cast<uint32_t*>(&h0);
        hp.y = *reinterpret_cast<uint32_t*>(&h1);
        *reinterpret_cast<uint2*>(uh + (tid >> 2) * UPH + (tid & 3) * 4) = hp;
    }
    __syncthreads();

    const int mA = tid / P;
    const int kA = tid & (P - 1);
    const bool validA = (kA < K);
    const int kAc = validA ? kA : (K - 1);
    uint4 zr0, zr1;
    {
        const uint4* rowA = reinterpret_cast<const uint4*>(
            xnormh + (size_t)nb[mA] * KD + kAc * 16);
        zr0 = __ldg(rowA);
        zr1 = __ldg(rowA + 1);
    }

    const int qB = tid >> 1;
    const int gB = tid & 1;
    const bool validB = (tid < 2 * Q);
    const int qc = validB ? qB : (Q - 1);
    const int kB = qc >> 2;
    uint2 zah[8];
#pragma unroll
    for (int j = 0; j < 8; ++j)
        zah[j] = __ldg(reinterpret_cast<const uint2*>(
            xnormh + (size_t)nb[8 * gB + j] * KD + qc * 4));
    float4 xs4 = __ldg(reinterpret_cast<const float4*>(xnorm + (size_t)n * KD) + qc);

#pragma unroll
    for (int t = 0; t < 5; ++t) {
        // ---- A: agreement p[m][k] = <z[m,k,:], u[k,:]> via HFMA2 ----
        float p;
        {
            const uint4* uptr = reinterpret_cast<const uint4*>(uh + kAc * UPH);
            uint4 u0 = uptr[0];
            uint4 u1 = uptr[1];
            __half2 za0 = __float2half2_rn(0.f);
            __half2 za1 = __float2half2_rn(0.f);
            za0 = __hfma2(u32_h2(zr0.x), u32_h2(u0.x), za0);
            za1 = __hfma2(u32_h2(zr0.y), u32_h2(u0.y), za1);
            za0 = __hfma2(u32_h2(zr0.z), u32_h2(u0.z), za0);
            za1 = __hfma2(u32_h2(zr0.w), u32_h2(u0.w), za1);
            za0 = __hfma2(u32_h2(zr1.x), u32_h2(u1.x), za0);
            za1 = __hfma2(u32_h2(zr1.y), u32_h2(u1.y), za1);
            za0 = __hfma2(u32_h2(zr1.z), u32_h2(u1.z), za0);
            za1 = __hfma2(u32_h2(zr1.w), u32_h2(u1.w), za1);
            float2 f0 = __half22float2(za0);
            float2 f1 = __half22float2(za1);
            float pv = (f0.x + f0.y) + (f1.x + f1.y);
            p = validA ? pv : -1e30f;
        }
        // softmax over capsules (no max-sub: |p|<=~1, padding exp -> 0)
        float e = __expf(p);
        float s = e;
        s += __shfl_xor_sync(0xffffffffu, s, 1);
        s += __shfl_xor_sync(0xffffffffu, s, 2);
        if (P == 8) s += __shfl_xor_sync(0xffffffffu, s, 4);
        float pr = __fdividef(e, s);
        if (validA) psh[kA * PSH + mA] = __float2half_rn(pr);
        __syncthreads();

        // ---- B: u[k][:] = xself + sum_m z[m][k][:] * p[m][k] via HFMA2 ----
        // pm vector: 8 halves = 16B, aligned (48*kB + 16*gB) -> 1 LDS.128
        uint4 pmv = *reinterpret_cast<const uint4*>(psh + kB * PSH + 8 * gB);
        uint32_t pmw[4] = {pmv.x, pmv.y, pmv.z, pmv.w};
        __half2 aA_lo = __float2half2_rn(0.f), aA_hi = __float2half2_rn(0.f);
        __half2 aB_lo = __float2half2_rn(0.f), aB_hi = __float2half2_rn(0.f);
#pragma unroll
        for (int w = 0; w < 4; ++w) {
            uint32_t lo_b = __byte_perm(pmw[w], pmw[w], 0x1010); // {m0,m0}
            uint32_t hi_b = __byte_perm(pmw[w], pmw[w], 0x3232); // {m1,m1}
            __half2 pm0 = u32_h2(lo_b);
            __half2 pm1 = u32_h2(hi_b);
            int j0 = 2 * w, j1 = 2 * w + 1;
            if (w < 2) {
                aA_lo = __hfma2(u32_h2(zah[j0].x), pm0, aA_lo);
                aA_hi = __hfma2(u32_h2(zah[j0].y), pm0, aA_hi);
                aA_lo = __hfma2(u32_h2(zah[j1].x), pm1, aA_lo);
                aA_hi = __hfma2(u32_h2(zah[j1].y), pm1, aA_hi);
            } else {
                aB_lo = __hfma2(u32_h2(zah[j0].x), pm0, aB_lo);
                aB_hi = __hfma2(u32_h2(zah[j0].y), pm0, aB_hi);
                aB_lo = __hfma2(u32_h2(zah[j1].x), pm1, aB_lo);
                aB_hi = __hfma2(u32_h2(zah[j1].y), pm1, aB_hi);
            }
        }
        float2 fA_lo = __half22float2(aA_lo);
        float2 fA_hi = __half22float2(aA_hi);
        float2 fB_lo = __half22float2(aB_lo);
        float2 fB_hi = __half22float2(aB_hi);
        float4 acc;
        acc.x = fA_lo.x + fB_lo.x;
        acc.y = fA_lo.y + fB_lo.y;
        acc.z = fA_hi.x + fB_hi.x;
        acc.w = fA_hi.y + fB_hi.y;

        acc.x += __shfl_xor_sync(0xffffffffu, acc.x, 1);
        acc.y += __shfl_xor_sync(0xffffffffu, acc.y, 1);
        acc.z += __shfl_xor_sync(0xffffffffu, acc.z, 1);
        acc.w += __shfl_xor_sync(0xffffffffu, acc.w, 1);
        acc.x += xs4.x; acc.y += xs4.y; acc.z += xs4.z; acc.w += xs4.w;

        if (t < 4) {
            float sq = acc.x * acc.x + acc.y * acc.y + acc.z * acc.z + acc.w * acc.w;
            sq += __shfl_xor_sync(0xffffffffu, sq, 2);
            sq += __shfl_xor_sync(0xffffffffu, sq, 4);
            float inv = rsqrtf(fmaxf(sq, 1e-24f));
            if (validB && gB == 0) {
                __half2 h0 = __floats2half2_rn(acc.x * inv, acc.y * inv);
                __half2 h1 = __floats2half2_rn(acc.z * inv, acc.w * inv);
                uint2 hp;
                hp.x = *reinterpret_cast<uint32_t*>(&h0);
                hp.y = *reinterpret_cast<uint32_t*>(&h1);
                *reinterpret_cast<uint2*>(uh + kB * UPH + (qB & 3) * 4) = hp;
            }
            __syncthreads();
        } else if (validB && gB == 0) {
            float4 o = make_float4(fmaxf(acc.x, 0.f), fmaxf(acc.y, 0.f),
                                   fmaxf(acc.z, 0.f), fmaxf(acc.w, 0.f));
            *reinterpret_cast<float4*>(outp + (size_t)n * OUTW + qB * 4) = o;
        }
    }
}

// ---------------------------------------------------------------------------
// host orchestration
// ---------------------------------------------------------------------------
extern "C" void kernel_launch(void* const* d_in, const int* in_sizes, int n_in,
                              void* d_out, int out_size)
{
    (void)in_sizes; (void)n_in; (void)out_size;
    const float* feature = (const float*)d_in[0];
    const int*   nbid    = (const int*)d_in[1];
    const float* pca_w   = (const float*)d_in[2];
    const float* pca_b   = (const float*)d_in[3];
    const float* W[6]  = {nullptr, (const float*)d_in[4], (const float*)d_in[6],
                          (const float*)d_in[8], (const float*)d_in[10], (const float*)d_in[12]};
    const float* Bb[6] = {nullptr, (const float*)d_in[5], (const float*)d_in[7],
                          (const float*)d_in[9], (const float*)d_in[11], (const float*)d_in[13]};
    float* out = (float*)d_out;

    static const int caps[6]   = {8, 7, 6, 5, 4, 3};
    static const int coloff[7] = {0, 128, 256, 368, 464, 544, 608};

    float* xnorm;
    __half* xnormh;
    cudaGetSymbolAddress((void**)&xnorm,  g_xnorm);
    cudaGetSymbolAddress((void**)&xnormh, g_xnormh);

    const int mblocks = (NNODES + BM - 1) / BM;   // 157

    // PCA: x0 = relu(feature @ pca_w.T + pca_b) -> out[:,0:128] + xnorm(+h)
    {
        dim3 grid((128 + BN - 1) / BN, mblocks);
        gemm_norm_kernel<true><<<grid, 256>>>(feature, FEAT, pca_w, FEAT, pca_b,
                                              out, OUTW, xnorm, xnormh,
                                              NNODES, 128, FEAT);
    }

    for (int i = 0; i < 6; ++i) {
        int k = caps[i];
        int kd = k * 16;
        if (i > 0) {
            int fin = caps[i - 1] * 16;
            dim3 grid((kd + BN - 1) / BN, mblocks);
            gemm_norm_kernel<false><<<grid, 256>>>(out + coloff[i], OUTW,
                                                   W[i], fin, Bb[i],
                                                   nullptr, 0, xnorm, xnormh,
                                                   NNODES, kd, fin);
        }
        float* dst = out + coloff[i + 1];
        switch (k) {
            case 8: routing_kernel<8><<<NNODES, 128>>>(xnorm, xnormh, nbid, dst); break;
            case 7: routing_kernel<7><<<NNODES, 128>>>(xnorm, xnormh, nbid, dst); break;
            case 6: routing_kernel<6><<<NNODES, 128>>>(xnorm, xnormh, nbid, dst); break;
            case 5: routing_kernel<5><<<NNODES, 128>>>(xnorm, xnormh, nbid, dst); break;
            case 4: routing_kernel<4><<<NNODES, 64>>>(xnorm, xnormh, nbid, dst); break;
            case 3: routing_kernel<3><<<NNODES, 64>>>(xnorm, xnormh, nbid, dst); break;
        }
    }
}

// round 15
// speedup vs baseline: 1.2212x; 1.0072x over previous
#include <cuda_runtime.h>
#include <cuda_fp16.h>
#include <cstdint>

// ---------------------------------------------------------------------------
// DisenGCN on GB300: fused GEMM(+bias+relu+capsule-normalize) + capsule routing
// N=20000, M=16 neighbors, FEAT=500, d=16, CAPS={8,7,6,5,4,3}, 5 routing iters
// GEMM mainloop: FFMA2 with M-paired accumulators (a-pairs straight from
// LDS.128, only b duplicated). Routing: full fp16-operand datapath.
// ---------------------------------------------------------------------------

#define NNODES 20000
#define MNBR   16
#define FEAT   500
#define OUTW   656

// scratch (device globals; no allocation allowed)
__device__ float  g_xnorm [NNODES * 128];  // fp32 normalized x
__device__ __half g_xnormh[NNODES * 128];  // fp16 mirror (neighbor gather)

// ---- packed f32x2 helpers (sm_103a FFMA2 via explicit PTX) ----------------
__device__ __forceinline__ unsigned long long f32x2_pack(float x, float y)
{
    unsigned long long r;
    asm("mov.b64 %0, {%1, %2};" : "=l"(r) : "f"(x), "f"(y));
    return r;
}
__device__ __forceinline__ void f32x2_unpack(unsigned long long v, float& x, float& y)
{
    asm("mov.b64 {%0, %1}, %2;" : "=f"(x), "=f"(y) : "l"(v));
}
__device__ __forceinline__ unsigned long long f32x2_fma(
    unsigned long long a, unsigned long long b, unsigned long long c)
{
    unsigned long long d;
    asm("fma.rn.f32x2 %0, %1, %2, %3;" : "=l"(d) : "l"(a), "l"(b), "l"(c));
    return d;
}
__device__ __forceinline__ __half2 u32_h2(uint32_t v)
{
    return *reinterpret_cast<__half2*>(&v);
}

// ---------------------------------------------------------------------------
// GEMM: val[M,N] = (relu?)(A[M,K] @ W[N,K]^T + bias[N])
// BM=128, BN=64, BKK=16, 256 threads; accumulators paired along M:
//   accp[p][j] = f32x2(C[2p][j], C[2p+1][j]); a-pairs come packed from As.
// ---------------------------------------------------------------------------
#define BM 128
#define BN 64
#define BKK 16

__device__ __forceinline__ float4 ldg4_guard(
    const float* __restrict__ P, int gr, int Rdim, int gc, int Kdim, int ld)
{
    float4 v = make_float4(0.f, 0.f, 0.f, 0.f);
    if (gr < Rdim) {
        if (gc + 3 < Kdim) {
            v = *reinterpret_cast<const float4*>(P + (size_t)gr * ld + gc);
        } else {
            const float* row = P + (size_t)gr * ld;
            if (gc + 0 < Kdim) v.x = row[gc + 0];
            if (gc + 1 < Kdim) v.y = row[gc + 1];
            if (gc + 2 < Kdim) v.z = row[gc + 2];
            if (gc + 3 < Kdim) v.w = row[gc + 3];
        }
    }
    return v;
}

template <bool WRITE_RAW>
__global__ void __launch_bounds__(256) gemm_norm_kernel(
    const float* __restrict__ A, int lda,
    const float* __restrict__ W, int ldw,
    const float* __restrict__ bias,
    float* __restrict__ rawOut, int ldo,
    float* __restrict__ xnorm,
    __half* __restrict__ xnormh,
    int Mdim, int Ndim, int Kdim)
{
    __shared__ float As[2][BKK][BM + 4];   // row stride 132 floats = 528B (16B-aligned)
    __shared__ float Ws[2][BKK][BN + 4];   // row stride 68 floats = 272B (16B-aligned)

    const int tid = threadIdx.x;
    const int tx = tid & 15;
    const int ty = tid >> 4;
    const int bm = blockIdx.y * BM;
    const int bn = blockIdx.x * BN;

    const int ar0 = tid >> 2;
    const int ac4 = (tid & 3) * 4;
    const int ar1 = (tid + 256) >> 2;
    const int wr  = tid >> 2;

    // accp[p][j]: rows (ty*8+2p, ty*8+2p+1), col tx*4+j
    unsigned long long accp[4][4];
    const unsigned long long zz = f32x2_pack(0.f, 0.f);
#pragma unroll
    for (int p = 0; p < 4; ++p)
#pragma unroll
        for (int j = 0; j < 4; ++j) accp[p][j] = zz;

    const int nk = (Kdim + BKK - 1) / BKK;

    float4 av0, av1, wv0;
    av0 = ldg4_guard(A, bm + ar0, Mdim, 0 + ac4, Kdim, lda);
    av1 = ldg4_guard(A, bm + ar1, Mdim, 0 + ac4, Kdim, lda);
    wv0 = ldg4_guard(W, bn + wr,  Ndim, 0 + ac4, Kdim, ldw);
    {
        As[0][ac4 + 0][ar0] = av0.x; As[0][ac4 + 1][ar0] = av0.y;
        As[0][ac4 + 2][ar0] = av0.z; As[0][ac4 + 3][ar0] = av0.w;
        As[0][ac4 + 0][ar1] = av1.x; As[0][ac4 + 1][ar1] = av1.y;
        As[0][ac4 + 2][ar1] = av1.z; As[0][ac4 + 3][ar1] = av1.w;
        Ws[0][ac4 + 0][wr]  = wv0.x; Ws[0][ac4 + 1][wr]  = wv0.y;
        Ws[0][ac4 + 2][wr]  = wv0.z; Ws[0][ac4 + 3][wr]  = wv0.w;
    }
    __syncthreads();

    for (int it = 0; it < nk; ++it) {
        const int buf = it & 1;
        if (it + 1 < nk) {
            int k0 = (it + 1) * BKK;
            av0 = ldg4_guard(A, bm + ar0, Mdim, k0 + ac4, Kdim, lda);
            av1 = ldg4_guard(A, bm + ar1, Mdim, k0 + ac4, Kdim, lda);
            wv0 = ldg4_guard(W, bn + wr,  Ndim, k0 + ac4, Kdim, ldw);
        }

#pragma unroll
        for (int kk = 0; kk < BKK; ++kk) {
            // a-pairs: rows ty*8..+7 -> 2x LDS.128 = 4 packed f32x2 (no movs)
            ulonglong2 ap01 = *reinterpret_cast<const ulonglong2*>(&As[buf][kk][ty * 8]);
            ulonglong2 ap23 = *reinterpret_cast<const ulonglong2*>(&As[buf][kk][ty * 8 + 4]);
            unsigned long long ap[4] = {ap01.x, ap01.y, ap23.x, ap23.y};
            // b: 1x LDS.128 + 4 dup movs
            float4 bv = *reinterpret_cast<const float4*>(&Ws[buf][kk][tx * 4]);
            unsigned long long bb[4];
            bb[0] = f32x2_pack(bv.x, bv.x);
            bb[1] = f32x2_pack(bv.y, bv.y);
            bb[2] = f32x2_pack(bv.z, bv.z);
            bb[3] = f32x2_pack(bv.w, bv.w);
#pragma unroll
            for (int p = 0; p < 4; ++p)
#pragma unroll
                for (int j = 0; j < 4; ++j)
                    accp[p][j] = f32x2_fma(ap[p], bb[j], accp[p][j]);
        }

        if (it + 1 < nk) {
            const int nbuf = buf ^ 1;
            As[nbuf][ac4 + 0][ar0] = av0.x; As[nbuf][ac4 + 1][ar0] = av0.y;
            As[nbuf][ac4 + 2][ar0] = av0.z; As[nbuf][ac4 + 3][ar0] = av0.w;
            As[nbuf][ac4 + 0][ar1] = av1.x; As[nbuf][ac4 + 1][ar1] = av1.y;
            As[nbuf][ac4 + 2][ar1] = av1.z; As[nbuf][ac4 + 3][ar1] = av1.w;
            Ws[nbuf][ac4 + 0][wr]  = wv0.x; Ws[nbuf][ac4 + 1][wr]  = wv0.y;
            Ws[nbuf][ac4 + 2][wr]  = wv0.z; Ws[nbuf][ac4 + 3][wr]  = wv0.w;
            __syncthreads();
        }
    }

    // ---- unpack row-paired accumulators ----
    float accf[8][4];
#pragma unroll
    for (int p = 0; p < 4; ++p)
#pragma unroll
        for (int j = 0; j < 4; ++j) {
            float lo, hi;
            f32x2_unpack(accp[p][j], lo, hi);
            accf[2 * p][j] = lo;
            accf[2 * p + 1][j] = hi;
        }

    // ---- epilogue: bias (+relu) + per-capsule L2 normalize ----
    const int gc0 = bn + tx * 4;
    float bvals[4];
#pragma unroll
    for (int j = 0; j < 4; ++j) bvals[j] = (gc0 + j < Ndim) ? bias[gc0 + j] : 0.f;

#pragma unroll
    for (int i = 0; i < 8; ++i) {
        int gr = bm + ty * 8 + i;
        float v[4];
        float ssq = 0.f;
#pragma unroll
        for (int j = 0; j < 4; ++j) {
            float val = (gc0 + j < Ndim) ? accf[i][j] + bvals[j] : 0.f;
            if (WRITE_RAW) val = fmaxf(val, 0.f);
            v[j] = val;
            ssq += val * val;
        }
        ssq += __shfl_xor_sync(0xffffffffu, ssq, 1);
        ssq += __shfl_xor_sync(0xffffffffu, ssq, 2);
        float inv = 1.f / fmaxf(sqrtf(ssq), 1e-12f);
        if (gr < Mdim && gc0 < Ndim) {
            if (WRITE_RAW) {
                float4 o = make_float4(v[0], v[1], v[2], v[3]);
                *reinterpret_cast<float4*>(rawOut + (size_t)gr * ldo + gc0) = o;
            }
            float4 no = make_float4(v[0] * inv, v[1] * inv, v[2] * inv, v[3] * inv);
            *reinterpret_cast<float4*>(xnorm + (size_t)gr * Ndim + gc0) = no;
            __half2 h0 = __floats2half2_rn(no.x, no.y);
            __half2 h1 = __floats2half2_rn(no.z, no.w);
            uint2 hp;
            hp.x = *reinterpret_cast<uint32_t*>(&h0);
            hp.y = *reinterpret_cast<uint32_t*>(&h1);
            *reinterpret_cast<uint2*>(xnormh + (size_t)gr * Ndim + gc0) = hp;
        }
    }
}

// ---------------------------------------------------------------------------
// Routing (R14 winner, unchanged): one CTA per node, NT = 16*P threads.
//  Phase A: z packed fp16 regs; u = 2 LDS.128 fp16; 8 HFMA2 split-acc dot.
//  Phase B: fp16 ps (k-major, stride 24 halves) -> 1 LDS.128; byte_perm
//           broadcasts; 16 HFMA2 depth-4 split accumulators; fp32 reductions.
// ---------------------------------------------------------------------------
template <int K>
__global__ void __launch_bounds__((K > 4) ? 128 : 64, (K > 4) ? 8 : 16)
routing_kernel(
    const float*  __restrict__ xnorm,
    const __half* __restrict__ xnormh,
    const int*    __restrict__ nbid,
    float* __restrict__ outp)
{
    constexpr int P  = (K > 4) ? 8 : 4;
    constexpr int KD = K * 16;
    constexpr int Q  = K * 4;
    constexpr int UPH = 24;                // u row stride (halves): 48B rows
    constexpr int PSH = 24;                // ps row stride (halves): 48B rows

    const int n = blockIdx.x;
    const int tid = threadIdx.x;

    __shared__ __align__(16) __half uh[8 * UPH];
    __shared__ __align__(16) __half psh[8 * PSH];  // k-major: psh[k*PSH + m]
    __shared__ int nb[16];

    if (tid < 16) nb[tid] = __ldg(nbid + n * MNBR + tid);

    if (tid < Q) {
        float4 v = reinterpret_cast<const float4*>(xnorm + (size_t)n * KD)[tid];
        __half2 h0 = __floats2half2_rn(v.x, v.y);
        __half2 h1 = __floats2half2_rn(v.z, v.w);
        uint2 hp;
        hp.x = *reinterpret_cast<uint32_t*>(&h0);
        hp.y = *reinterpret_cast<uint32_t*>(&h1);
        *reinterpret_cast<uint2*>(uh + (tid >> 2) * UPH + (tid & 3) * 4) = hp;
    }
    __syncthreads();

    const int mA = tid / P;
    const int kA = tid & (P - 1);
    const bool validA = (kA < K);
    const int kAc = validA ? kA : (K - 1);
    uint4 zr0, zr1;
    {
        const uint4* rowA = reinterpret_cast<const uint4*>(
            xnormh + (size_t)nb[mA] * KD + kAc * 16);
        zr0 = __ldg(rowA);
        zr1 = __ldg(rowA + 1);
    }

    const int qB = tid >> 1;
    const int gB = tid & 1;
    const bool validB = (tid < 2 * Q);
    const int qc = validB ? qB : (Q - 1);
    const int kB = qc >> 2;
    uint2 zah[8];
#pragma unroll
    for (int j = 0; j < 8; ++j)
        zah[j] = __ldg(reinterpret_cast<const uint2*>(
            xnormh + (size_t)nb[8 * gB + j] * KD + qc * 4));
    float4 xs4 = __ldg(reinterpret_cast<const float4*>(xnorm + (size_t)n * KD) + qc);

#pragma unroll
    for (int t = 0; t < 5; ++t) {
        // ---- A: agreement p[m][k] = <z[m,k,:], u[k,:]> via HFMA2 ----
        float p;
        {
            const uint4* uptr = reinterpret_cast<const uint4*>(uh + kAc * UPH);
            uint4 u0 = uptr[0];
            uint4 u1 = uptr[1];
            __half2 za0 = __float2half2_rn(0.f);
            __half2 za1 = __float2half2_rn(0.f);
            za0 = __hfma2(u32_h2(zr0.x), u32_h2(u0.x), za0);
            za1 = __hfma2(u32_h2(zr0.y), u32_h2(u0.y), za1);
            za0 = __hfma2(u32_h2(zr0.z), u32_h2(u0.z), za0);
            za1 = __hfma2(u32_h2(zr0.w), u32_h2(u0.w), za1);
            za0 = __hfma2(u32_h2(zr1.x), u32_h2(u1.x), za0);
            za1 = __hfma2(u32_h2(zr1.y), u32_h2(u1.y), za1);
            za0 = __hfma2(u32_h2(zr1.z), u32_h2(u1.z), za0);
            za1 = __hfma2(u32_h2(zr1.w), u32_h2(u1.w), za1);
            float2 f0 = __half22float2(za0);
            float2 f1 = __half22float2(za1);
            float pv = (f0.x + f0.y) + (f1.x + f1.y);
            p = validA ? pv : -1e30f;
        }
        // softmax over capsules (no max-sub: |p|<=~1, padding exp -> 0)
        float e = __expf(p);
        float s = e;
        s += __shfl_xor_sync(0xffffffffu, s, 1);
        s += __shfl_xor_sync(0xffffffffu, s, 2);
        if (P == 8) s += __shfl_xor_sync(0xffffffffu, s, 4);
        float pr = __fdividef(e, s);
        if (validA) psh[kA * PSH + mA] = __float2half_rn(pr);
        __syncthreads();

        // ---- B: u[k][:] = xself + sum_m z[m][k][:] * p[m][k] via HFMA2 ----
        uint4 pmv = *reinterpret_cast<const uint4*>(psh + kB * PSH + 8 * gB);
        uint32_t pmw[4] = {pmv.x, pmv.y, pmv.z, pmv.w};
        __half2 aA_lo = __float2half2_rn(0.f), aA_hi = __float2half2_rn(0.f);
        __half2 aB_lo = __float2half2_rn(0.f), aB_hi = __float2half2_rn(0.f);
#pragma unroll
        for (int w = 0; w < 4; ++w) {
            uint32_t lo_b = __byte_perm(pmw[w], pmw[w], 0x1010);
            uint32_t hi_b = __byte_perm(pmw[w], pmw[w], 0x3232);
            __half2 pm0 = u32_h2(lo_b);
            __half2 pm1 = u32_h2(hi_b);
            int j0 = 2 * w, j1 = 2 * w + 1;
            if (w < 2) {
                aA_lo = __hfma2(u32_h2(zah[j0].x), pm0, aA_lo);
                aA_hi = __hfma2(u32_h2(zah[j0].y), pm0, aA_hi);
                aA_lo = __hfma2(u32_h2(zah[j1].x), pm1, aA_lo);
                aA_hi = __hfma2(u32_h2(zah[j1].y), pm1, aA_hi);
            } else {
                aB_lo = __hfma2(u32_h2(zah[j0].x), pm0, aB_lo);
                aB_hi = __hfma2(u32_h2(zah[j0].y), pm0, aB_hi);
                aB_lo = __hfma2(u32_h2(zah[j1].x), pm1, aB_lo);
                aB_hi = __hfma2(u32_h2(zah[j1].y), pm1, aB_hi);
            }
        }
        float2 fA_lo = __half22float2(aA_lo);
        float2 fA_hi = __half22float2(aA_hi);
        float2 fB_lo = __half22float2(aB_lo);
        float2 fB_hi = __half22float2(aB_hi);
        float4 acc;
        acc.x = fA_lo.x + fB_lo.x;
        acc.y = fA_lo.y + fB_lo.y;
        acc.z = fA_hi.x + fB_hi.x;
        acc.w = fA_hi.y + fB_hi.y;

        acc.x += __shfl_xor_sync(0xffffffffu, acc.x, 1);
        acc.y += __shfl_xor_sync(0xffffffffu, acc.y, 1);
        acc.z += __shfl_xor_sync(0xffffffffu, acc.z, 1);
        acc.w += __shfl_xor_sync(0xffffffffu, acc.w, 1);
        acc.x += xs4.x; acc.y += xs4.y; acc.z += xs4.z; acc.w += xs4.w;

        if (t < 4) {
            float sq = acc.x * acc.x + acc.y * acc.y + acc.z * acc.z + acc.w * acc.w;
            sq += __shfl_xor_sync(0xffffffffu, sq, 2);
            sq += __shfl_xor_sync(0xffffffffu, sq, 4);
            float inv = rsqrtf(fmaxf(sq, 1e-24f));
            if (validB && gB == 0) {
                __half2 h0 = __floats2half2_rn(acc.x * inv, acc.y * inv);
                __half2 h1 = __floats2half2_rn(acc.z * inv, acc.w * inv);
                uint2 hp;
                hp.x = *reinterpret_cast<uint32_t*>(&h0);
                hp.y = *reinterpret_cast<uint32_t*>(&h1);
                *reinterpret_cast<uint2*>(uh + kB * UPH + (qB & 3) * 4) = hp;
            }
            __syncthreads();
        } else if (validB && gB == 0) {
            float4 o = make_float4(fmaxf(acc.x, 0.f), fmaxf(acc.y, 0.f),
                                   fmaxf(acc.z, 0.f), fmaxf(acc.w, 0.f));
            *reinterpret_cast<float4*>(outp + (size_t)n * OUTW + qB * 4) = o;
        }
    }
}

// ---------------------------------------------------------------------------
// host orchestration
// ---------------------------------------------------------------------------
extern "C" void kernel_launch(void* const* d_in, const int* in_sizes, int n_in,
                              void* d_out, int out_size)
{
    (void)in_sizes; (void)n_in; (void)out_size;
    const float* feature = (const float*)d_in[0];
    const int*   nbid    = (const int*)d_in[1];
    const float* pca_w   = (const float*)d_in[2];
    const float* pca_b   = (const float*)d_in[3];
    const float* W[6]  = {nullptr, (const float*)d_in[4], (const float*)d_in[6],
                          (const float*)d_in[8], (const float*)d_in[10], (const float*)d_in[12]};
    const float* Bb[6] = {nullptr, (const float*)d_in[5], (const float*)d_in[7],
                          (const float*)d_in[9], (const float*)d_in[11], (const float*)d_in[13]};
    float* out = (float*)d_out;

    static const int caps[6]   = {8, 7, 6, 5, 4, 3};
    static const int coloff[7] = {0, 128, 256, 368, 464, 544, 608};

    float* xnorm;
    __half* xnormh;
    cudaGetSymbolAddress((void**)&xnorm,  g_xnorm);
    cudaGetSymbolAddress((void**)&xnormh, g_xnormh);

    const int mblocks = (NNODES + BM - 1) / BM;   // 157

    // PCA: x0 = relu(feature @ pca_w.T + pca_b) -> out[:,0:128] + xnorm(+h)
    {
        dim3 grid((128 + BN - 1) / BN, mblocks);
        gemm_norm_kernel<true><<<grid, 256>>>(feature, FEAT, pca_w, FEAT, pca_b,
                                              out, OUTW, xnorm, xnormh,
                                              NNODES, 128, FEAT);
    }

    for (int i = 0; i < 6; ++i) {
        int k = caps[i];
        int kd = k * 16;
        if (i > 0) {
            int fin = caps[i - 1] * 16;
            dim3 grid((kd + BN - 1) / BN, mblocks);
            gemm_norm_kernel<false><<<grid, 256>>>(out + coloff[i], OUTW,
                                                   W[i], fin, Bb[i],
                                                   nullptr, 0, xnorm, xnormh,
                                                   NNODES, kd, fin);
        }
        float* dst = out + coloff[i + 1];
        switch (k) {
            case 8: routing_kernel<8><<<NNODES, 128>>>(xnorm, xnormh, nbid, dst); break;
            case 7: routing_kernel<7><<<NNODES, 128>>>(xnorm, xnormh, nbid, dst); break;
            case 6: routing_kernel<6><<<NNODES, 128>>>(xnorm, xnormh, nbid, dst); break;
            case 5: routing_kernel<5><<<NNODES, 128>>>(xnorm, xnormh, nbid, dst); break;
            case 4: routing_kernel<4><<<NNODES, 64>>>(xnorm, xnormh, nbid, dst); break;
            case 3: routing_kernel<3><<<NNODES, 64>>>(xnorm, xnormh, nbid, dst); break;
        }
    }
}